// round 16
// baseline (speedup 1.0000x reference)
#include <cuda_runtime.h>
#include <cuda_pipeline.h>

// Sobel_16724602651101 — R15
// x: (16, 3, 512, 512) fp32 -> out: [magnitude | angle] each (16,512,512) fp32.
//
// Tile-persistent cp.async pipeline: each block walks 4 consecutive 128x16
// y-tiles. smem planes: ch0 double-buffered (s[0]/s[1]), ch1/ch2 single
// (s[2]/s[3]). Per tile: wait ch0 -> barrier -> issue ch1/2(t) + ch0(t+1)
// -> compute ch0 (overlapping both) -> wait ch1/2 -> barrier -> compute
// ch1/2 + store. The ch0 DRAM bubble is paid once per 4 tiles, not per tile.
// 32-bit output indexing. Numeric trees frozen from the R1-R14 lineage
// (R1 grouping, exact power-of-two deferred scaling, sqrt.approx +
// __fdividef; rel_err 1.0849e-7).

#define BATCH 16
#define CH 3
#define HH 512
#define WW 512
#define HW (HH * WW)

#define TILE_W 128
#define TILE_H 16
#define T_TILES 4        // tiles per block (walked in +y)
#define LH 18            // halo rows per plane
#define LPITCH 136       // halo cols: j <-> global col bx0-4+j ; used j = 3..132

#define EPS64 (64.0f * 1e-9f)
#define TINY8 (8.0f * 1e-9f)

__device__ __forceinline__ float fsqrt_approx(float a)
{
    float r;
    asm("sqrt.approx.f32 %0, %1;" : "=f"(r) : "f"(a));
    return r;
}

// async-load one channel plane (18 halo rows) of the tile whose first output
// row is by0. warp=row, lane=16B group; no div/mod.
__device__ __forceinline__ void load_plane(
    float (*dst)[LPITCH], const float* __restrict__ xc,
    int by0, int wid, int lane, int col_a, int col_b)
{
    #pragma unroll
    for (int k = 0; k < 3; k++) {
        const int r = wid + 8 * k;                 // 0..23; valid r < 18
        if (k < 2 || wid < 2) {
            const int gr = min(max(by0 - 1 + r, 0), HH - 1);
            const float* __restrict__ rp = xc + gr * WW;
            __pipeline_memcpy_async(&dst[r][4 * lane], rp + col_a, 16);
            if (lane < 2)
                __pipeline_memcpy_async(&dst[r][128 + 4 * lane], rp + col_b, 16);
        }
    }
}

// accumulate one channel from its smem plane into the per-thread argmax state
template <bool FIRST>
__device__ __forceinline__ void compute_channel(
    const float (*sc)[LPITCH], int lc, int wy, bool fixL, bool fixR,
    float bm[2][4], float bgx[2][4], float bgy[2][4])
{
    // 4 input rows (local 2wy..2wy+3) x 6 cols
    float w[4][6];
    #pragma unroll
    for (int i = 0; i < 4; i++) {
        const float* __restrict__ row = &sc[2 * wy + i][0];
        float2 va = *(const float2*)(row + lc + 2);   // cols lc+2, lc+3
        float4 v  = *(const float4*)(row + lc + 4);   // cols lc+4..lc+7
        float2 vb = *(const float2*)(row + lc + 8);   // cols lc+8, lc+9
        w[i][0] = fixL ? v.x : va.y;                  // replicate pad: col -1 := col 0
        w[i][1] = v.x; w[i][2] = v.y; w[i][3] = v.z; w[i][4] = v.w;
        w[i][5] = fixR ? v.w : vb.x;                  // col 512 := col 511
    }

    // horizontal diffs once per input row (rows 1,2 shared by both outputs)
    float dr[4][4];
    #pragma unroll
    for (int i = 0; i < 4; i++)
        #pragma unroll
        for (int p = 0; p < 4; p++) dr[i][p] = w[i][p + 2] - w[i][p];

    // vertical diffs per output row
    float vd[2][6];
    #pragma unroll
    for (int j = 0; j < 6; j++) { vd[0][j] = w[2][j] - w[0][j];
                                  vd[1][j] = w[3][j] - w[1][j]; }

    #pragma unroll
    for (int rr = 0; rr < 2; rr++) {
        #pragma unroll
        for (int p = 0; p < 4; p++) {
            // 8x-scaled gx/gy, R1's exact grouping
            float gx = dr[rr][p] + 2.0f * dr[rr + 1][p] + dr[rr + 2][p];
            float gy = vd[rr][p] + 2.0f * vd[rr][p + 1] + vd[rr][p + 2];
            float m  = gx * gx + gy * gy + EPS64;      // 64x-scaled
            if (FIRST) {
                bm[rr][p] = m; bgx[rr][p] = gx; bgy[rr][p] = gy;
            } else if (m > bm[rr][p]) {   // strict >: first-occurrence argmax
                bm[rr][p] = m; bgx[rr][p] = gx; bgy[rr][p] = gy;
            }
        }
    }
}

__global__ __launch_bounds__(256, 4)
void sobel_kernel(const float* __restrict__ x, float* __restrict__ out)
{
    // planes: s[0]/s[1] = ch0 double buffer; s[2] = ch1; s[3] = ch2
    __shared__ __align__(16) float s[4][LH][LPITCH];

    const int bx0 = blockIdx.x * TILE_W;
    const int byb = blockIdx.y * (T_TILES * TILE_H);   // block's first out row
    const int b   = blockIdx.z;
    const int tid = threadIdx.x;
    const int lane = tid & 31;
    const int wid  = tid >> 5;

    const float* __restrict__ xb = x + (size_t)b * CH * HW;
    const float* __restrict__ x0 = xb;
    const float* __restrict__ x1 = xb + HW;
    const float* __restrict__ x2 = xb + 2 * HW;

    const bool fixL = (bx0 == 0) && (lane == 0);
    const bool fixR = (bx0 + TILE_W == WW) && (lane == 31);

    const int col_a = min(max(bx0 - 4 + 4 * lane, 0), WW - 4);
    const int col_b = min(max(bx0 + 124 + 4 * lane, 0), WW - 4);

    const int lc = 4 * lane;                      // window local cols lc+3..lc+8
    const int wy = wid;                           // out rows by0+2wy, +2wy+1

    // preamble: A0 = ch0(tile0); B0 = ch1/2(tile0)
    load_plane(s[0], x0, byb, wid, lane, col_a, col_b);
    __pipeline_commit();                                        // A_0
    load_plane(s[2], x1, byb, wid, lane, col_a, col_b);
    load_plane(s[3], x2, byb, wid, lane, col_a, col_b);
    __pipeline_commit();                                        // B_0

    #pragma unroll
    for (int t = 0; t < T_TILES; t++) {
        const int by0 = byb + t * TILE_H;

        // wait for A_t (ch0 of this tile); B_t may still be in flight at t=0
        __pipeline_wait_prior(t == 0 ? 1 : 0);
        __syncthreads();   // ch0(t) visible; all warps done with tile t-1

        // overwrites below are safe: barrier above proves tile t-1 fully read
        if (t >= 1) {
            load_plane(s[2], x1, by0, wid, lane, col_a, col_b);
            load_plane(s[3], x2, by0, wid, lane, col_a, col_b);
            __pipeline_commit();                                // B_t
        }
        if (t + 1 < T_TILES) {
            load_plane(s[(t + 1) & 1], x0, by0 + TILE_H, wid, lane, col_a, col_b);
            __pipeline_commit();                                // A_{t+1}
        }

        float bm[2][4], bgx[2][4], bgy[2][4];
        compute_channel<true>(s[t & 1], lc, wy, fixL, fixR, bm, bgx, bgy);

        // B_t landed (A_{t+1}, if any, may keep flying)
        __pipeline_wait_prior((t + 1 < T_TILES) ? 1 : 0);
        __syncthreads();

        compute_channel<false>(s[2], lc, wy, fixL, fixR, bm, bgx, bgy);
        compute_channel<false>(s[3], lc, wy, fixL, fixR, bm, bgx, bgy);

        // epilogue + store (32-bit float offsets; total output 8.4M floats)
        const int obase = b * HW + (by0 + 2 * wy) * WW + (bx0 + lc);

        #pragma unroll
        for (int rr = 0; rr < 2; rr++) {
            float4 mag, ang;
            mag.x = fsqrt_approx(bm[rr][0]) * 0.125f;   // == sqrt(m)/8 bitwise
            mag.y = fsqrt_approx(bm[rr][1]) * 0.125f;
            mag.z = fsqrt_approx(bm[rr][2]) * 0.125f;
            mag.w = fsqrt_approx(bm[rr][3]) * 0.125f;

            float y0 = (bgy[rr][0] == 0.f) ? TINY8 : bgy[rr][0];
            float y1 = (bgy[rr][1] == 0.f) ? TINY8 : bgy[rr][1];
            float y2 = (bgy[rr][2] == 0.f) ? TINY8 : bgy[rr][2];
            float y3 = (bgy[rr][3] == 0.f) ? TINY8 : bgy[rr][3];
            ang.x = fminf(fmaxf(__fdividef(bgx[rr][0], y0), -10.f), 10.f);
            ang.y = fminf(fmaxf(__fdividef(bgx[rr][1], y1), -10.f), 10.f);
            ang.z = fminf(fmaxf(__fdividef(bgx[rr][2], y2), -10.f), 10.f);
            ang.w = fminf(fmaxf(__fdividef(bgx[rr][3], y3), -10.f), 10.f);

            const int o = obase + rr * WW;
            *(float4*)(out + o)              = mag;
            *(float4*)(out + BATCH * HW + o) = ang;
        }
    }
}

extern "C" void kernel_launch(void* const* d_in, const int* in_sizes, int n_in,
                              void* d_out, int out_size)
{
    const float* x = (const float*)d_in[0];
    float* out = (float*)d_out;

    dim3 block(256, 1, 1);
    dim3 grid(WW / TILE_W, HH / (T_TILES * TILE_H), BATCH);   // (4, 8, 16) = 512
    sobel_kernel<<<grid, block>>>(x, out);
}

// round 17
// speedup vs baseline: 1.2073x; 1.2073x over previous
#include <cuda_runtime.h>
#include <cuda_pipeline.h>

// Sobel_16724602651101 — R16
// x: (16, 3, 512, 512) fp32 -> out: [magnitude | angle] each (16,512,512) fp32.
//
// R14 skeleton (two-stage cp.async channel pipeline, 2 barriers, 2048 blocks)
// + LDS-wavefront cut: one aligned LDS.128 per row-channel, halo columns via
// warp shuffles (register exchange instead of misaligned smem reads);
// lane-0/31 patches + image-edge replicate folded into the same predicates.
// 32-bit output indexing. Numeric trees frozen from the R1-R15 lineage
// (R1 grouping, exact power-of-two deferred scaling, sqrt.approx +
// __fdividef; rel_err 1.0849e-7).

#define BATCH 16
#define CH 3
#define HH 512
#define WW 512
#define HW (HH * WW)

#define TILE_W 128
#define TILE_H 16
#define LH 18            // halo rows per channel
#define LPITCH 136       // halo cols: j <-> global col bx0-4+j ; used j = 3..132

#define FULLMASK 0xFFFFFFFFu
#define EPS64 (64.0f * 1e-9f)
#define TINY8 (8.0f * 1e-9f)

__device__ __forceinline__ float fsqrt_approx(float a)
{
    float r;
    asm("sqrt.approx.f32 %0, %1;" : "=f"(r) : "f"(a));
    return r;
}

// accumulate one channel from its smem plane into the per-thread argmax state.
// One aligned LDS.128 per row; halo cols via shuffles; lane-edge patches
// (incl. image-edge replicate) predicated.
template <bool FIRST>
__device__ __forceinline__ void compute_channel(
    const float (*sc)[LPITCH], int lc, int wy, int lane, bool edgeL, bool edgeR,
    float bm[2][4], float bgx[2][4], float bgy[2][4])
{
    float w[4][6];
    #pragma unroll
    for (int i = 0; i < 4; i++) {
        const float* __restrict__ row = &sc[2 * wy + i][0];
        float4 v = *(const float4*)(row + lc + 4);        // cols px..px+3
        float lf = __shfl_up_sync(FULLMASK, v.w, 1);      // col px-1 (from prev lane)
        float rt = __shfl_down_sync(FULLMASK, v.x, 1);    // col px+4 (from next lane)
        if (lane == 0)  lf = edgeL ? v.x : row[lc + 3];   // replicate or smem halo
        if (lane == 31) rt = edgeR ? v.w : row[lc + 8];
        w[i][0] = lf;
        w[i][1] = v.x; w[i][2] = v.y; w[i][3] = v.z; w[i][4] = v.w;
        w[i][5] = rt;
    }

    // horizontal diffs once per input row (rows 1,2 shared by both outputs)
    float dr[4][4];
    #pragma unroll
    for (int i = 0; i < 4; i++)
        #pragma unroll
        for (int p = 0; p < 4; p++) dr[i][p] = w[i][p + 2] - w[i][p];

    // vertical diffs per output row
    float vd[2][6];
    #pragma unroll
    for (int j = 0; j < 6; j++) { vd[0][j] = w[2][j] - w[0][j];
                                  vd[1][j] = w[3][j] - w[1][j]; }

    #pragma unroll
    for (int rr = 0; rr < 2; rr++) {
        #pragma unroll
        for (int p = 0; p < 4; p++) {
            // 8x-scaled gx/gy, R1's exact grouping
            float gx = dr[rr][p] + 2.0f * dr[rr + 1][p] + dr[rr + 2][p];
            float gy = vd[rr][p] + 2.0f * vd[rr][p + 1] + vd[rr][p + 2];
            float m  = gx * gx + gy * gy + EPS64;      // 64x-scaled
            if (FIRST) {
                bm[rr][p] = m; bgx[rr][p] = gx; bgy[rr][p] = gy;
            } else if (m > bm[rr][p]) {   // strict >: first-occurrence argmax
                bm[rr][p] = m; bgx[rr][p] = gx; bgy[rr][p] = gy;
            }
        }
    }
}

__global__ __launch_bounds__(256, 4)
void sobel_kernel(const float* __restrict__ x, float* __restrict__ out)
{
    __shared__ __align__(16) float s[CH][LH][LPITCH];

    const int bx0 = blockIdx.x * TILE_W;
    const int by0 = blockIdx.y * TILE_H;
    const int b   = blockIdx.z;
    const int tid = threadIdx.x;
    const int lane = tid & 31;
    const int wid  = tid >> 5;

    const float* __restrict__ xb = x + (size_t)b * CH * HW;

    const bool edgeL = (bx0 == 0);
    const bool edgeR = (bx0 + TILE_W == WW);

    // ---- load phase: warp=row, lane=16B group; no div/mod ----
    const int col_a = min(max(bx0 - 4 + 4 * lane, 0), WW - 4);
    const int col_b = min(max(bx0 + 124 + 4 * lane, 0), WW - 4);

    // stage A: channel 0
    {
        const float* __restrict__ xc = xb;
        #pragma unroll
        for (int k = 0; k < 3; k++) {
            const int r = wid + 8 * k;
            if (k < 2 || wid < 2) {
                const int gr = min(max(by0 - 1 + r, 0), HH - 1);
                const float* __restrict__ rp = xc + gr * WW;
                __pipeline_memcpy_async(&s[0][r][4 * lane], rp + col_a, 16);
                if (lane < 2)
                    __pipeline_memcpy_async(&s[0][r][128 + 4 * lane], rp + col_b, 16);
            }
        }
    }
    __pipeline_commit();

    // stage B: channels 1, 2
    #pragma unroll
    for (int c = 1; c < CH; c++) {
        const float* __restrict__ xc = xb + c * HW;
        #pragma unroll
        for (int k = 0; k < 3; k++) {
            const int r = wid + 8 * k;
            if (k < 2 || wid < 2) {
                const int gr = min(max(by0 - 1 + r, 0), HH - 1);
                const float* __restrict__ rp = xc + gr * WW;
                __pipeline_memcpy_async(&s[c][r][4 * lane], rp + col_a, 16);
                if (lane < 2)
                    __pipeline_memcpy_async(&s[c][r][128 + 4 * lane], rp + col_b, 16);
            }
        }
    }
    __pipeline_commit();

    const int lc = 4 * lane;                      // thread px cols bx0+lc..+3
    const int wy = wid;                           // out rows by0+2wy, +2wy+1

    float bm[2][4], bgx[2][4], bgy[2][4];

    // compute ch0 while ch1/ch2 LDGSTS are still in flight
    __pipeline_wait_prior(1);
    __syncthreads();
    compute_channel<true>(s[0], lc, wy, lane, edgeL, edgeR, bm, bgx, bgy);

    // then the remaining channels
    __pipeline_wait_prior(0);
    __syncthreads();
    compute_channel<false>(s[1], lc, wy, lane, edgeL, edgeR, bm, bgx, bgy);
    compute_channel<false>(s[2], lc, wy, lane, edgeL, edgeR, bm, bgx, bgy);

    // epilogue + store (32-bit offsets: total output 8.4M floats < 2^31)
    const int obase = b * HW + (by0 + 2 * wy) * WW + (bx0 + lc);

    #pragma unroll
    for (int rr = 0; rr < 2; rr++) {
        float4 mag, ang;
        mag.x = fsqrt_approx(bm[rr][0]) * 0.125f;   // == sqrt(m)/8 bitwise
        mag.y = fsqrt_approx(bm[rr][1]) * 0.125f;
        mag.z = fsqrt_approx(bm[rr][2]) * 0.125f;
        mag.w = fsqrt_approx(bm[rr][3]) * 0.125f;

        float y0 = (bgy[rr][0] == 0.f) ? TINY8 : bgy[rr][0];
        float y1 = (bgy[rr][1] == 0.f) ? TINY8 : bgy[rr][1];
        float y2 = (bgy[rr][2] == 0.f) ? TINY8 : bgy[rr][2];
        float y3 = (bgy[rr][3] == 0.f) ? TINY8 : bgy[rr][3];
        ang.x = fminf(fmaxf(__fdividef(bgx[rr][0], y0), -10.f), 10.f);
        ang.y = fminf(fmaxf(__fdividef(bgx[rr][1], y1), -10.f), 10.f);
        ang.z = fminf(fmaxf(__fdividef(bgx[rr][2], y2), -10.f), 10.f);
        ang.w = fminf(fmaxf(__fdividef(bgx[rr][3], y3), -10.f), 10.f);

        const int o = obase + rr * WW;
        *(float4*)(out + o)              = mag;
        *(float4*)(out + BATCH * HW + o) = ang;
    }
}

extern "C" void kernel_launch(void* const* d_in, const int* in_sizes, int n_in,
                              void* d_out, int out_size)
{
    const float* x = (const float*)d_in[0];
    float* out = (float*)d_out;

    dim3 block(256, 1, 1);
    dim3 grid(WW / TILE_W, HH / TILE_H, BATCH);   // (4, 32, 16) = 2048 blocks
    sobel_kernel<<<grid, block>>>(x, out);
}